// round 9
// baseline (speedup 1.0000x reference)
#include <cuda_runtime.h>
#include <cuda.h>
#include <cstdint>

#define DIM 256
#define OUT 8
#define CHUNK 32          // floats per chunk = 128B row piece (SW128 box width)
#define NCHUNK 8          // DIM / CHUNK
#define TPW 32            // tokens per warp group (1 per lane)
#define WARPS 8           // warps per block

#define TILE_BYTES  (TPW * CHUNK * 4)           // 4096 per stage
#define XBUF_BYTES  (WARPS * 2 * TILE_BYTES)    // 65536
#define WP_BYTES    (DIM / 2 * OUT * 8)         // 8192
#define TAIL_BYTES  (16 * 8 + 96 * 4)           // 16 mbarriers + params
#define SMEM_TOTAL  (1024 + XBUF_BYTES + WP_BYTES + TAIL_BYTES)   // ~75KB -> 3 blocks/SM

__device__ __forceinline__ unsigned long long pk2(float lo, float hi) {
    unsigned long long r;
    asm("mov.b64 %0, {%1,%2};" : "=l"(r) : "f"(lo), "f"(hi));
    return r;
}
__device__ __forceinline__ unsigned long long fma2(unsigned long long a, unsigned long long b,
                                                   unsigned long long c) {
    unsigned long long d;
    asm("fma.rn.f32x2 %0, %1, %2, %3;" : "=l"(d) : "l"(a), "l"(b), "l"(c));
    return d;
}

__device__ __forceinline__ void mbar_init(uint32_t mbar, uint32_t cnt) {
    asm volatile("mbarrier.init.shared.b64 [%0], %1;" :: "r"(mbar), "r"(cnt) : "memory");
}
__device__ __forceinline__ void mbar_expect_tx(uint32_t mbar, uint32_t bytes) {
    asm volatile("mbarrier.arrive.expect_tx.shared.b64 _, [%0], %1;" :: "r"(mbar), "r"(bytes) : "memory");
}
__device__ __forceinline__ void mbar_wait(uint32_t mbar, uint32_t parity) {
    uint32_t done;
    asm volatile(
        "{\n\t.reg .pred p;\n\t"
        "mbarrier.try_wait.parity.acquire.cta.shared::cta.b64 p, [%1], %2;\n\t"
        "selp.b32 %0, 1, 0, p;\n\t}"
        : "=r"(done) : "r"(mbar), "r"(parity) : "memory");
    if (!done) {
        asm volatile(
            "{\n\t.reg .pred P1;\n\t"
            "WL_%=:\n\t"
            "mbarrier.try_wait.parity.acquire.cta.shared::cta.b64 P1, [%0], %1, 0x989680;\n\t"
            "@P1 bra.uni WD_%=;\n\t"
            "bra.uni WL_%=;\n\t"
            "WD_%=:\n\t}"
            :: "r"(mbar), "r"(parity) : "memory");
    }
}
__device__ __forceinline__ void tma_load_2d(uint32_t dst, const void* tmap,
                                            int cx, int cy, uint32_t mbar) {
    asm volatile(
        "cp.async.bulk.tensor.2d.shared::cta.global.tile.mbarrier::complete_tx::bytes "
        "[%0], [%1, {%2, %3}], [%4];"
        :: "r"(dst), "l"(tmap), "r"(cx), "r"(cy), "r"(mbar) : "memory");
}

struct EpiParams { const float *W2, *b1, *b2, *g, *bt; };

__device__ __forceinline__ void epilogue(const unsigned long long* acc, const EpiParams& ep,
                                         float* __restrict__ out, int tok)
{
    float gg[OUT];
    #pragma unroll
    for (int o = 0; o < OUT; o++) {
        float2 p = *(const float2*)&acc[o];
        float hv = p.x + p.y + ep.b1[o];
        gg[o] = 0.5f * hv * (1.0f + erff(hv * 0.70710678118654752440f));
    }
    float y[OUT];
    #pragma unroll
    for (int p = 0; p < OUT; p++) {
        float s = ep.b2[p];
        #pragma unroll
        for (int o = 0; o < OUT; o++) s = fmaf(ep.W2[p * 8 + o], gg[o], s);
        y[p] = s;
    }
    float mu = 0.0f;
    #pragma unroll
    for (int p = 0; p < OUT; p++) mu += y[p];
    mu *= 0.125f;
    float var = 0.0f;
    #pragma unroll
    for (int p = 0; p < OUT; p++) { float d = y[p] - mu; var = fmaf(d, d, var); }
    var *= 0.125f;
    float rs = rsqrtf(var + 1e-5f);

    float4 o0, o1;
    o0.x = (y[0] - mu) * rs * ep.g[0] + ep.bt[0];
    o0.y = (y[1] - mu) * rs * ep.g[1] + ep.bt[1];
    o0.z = (y[2] - mu) * rs * ep.g[2] + ep.bt[2];
    o0.w = (y[3] - mu) * rs * ep.g[3] + ep.bt[3];
    o1.x = (y[4] - mu) * rs * ep.g[4] + ep.bt[4];
    o1.y = (y[5] - mu) * rs * ep.g[5] + ep.bt[5];
    o1.z = (y[6] - mu) * rs * ep.g[6] + ep.bt[6];
    o1.w = (y[7] - mu) * rs * ep.g[7] + ep.bt[7];
    float4* op = (float4*)(out + (size_t)tok * 8);
    op[0] = o0;
    op[1] = o1;
}

__global__ __launch_bounds__(256, 3)
void ffn_kernel(const __grid_constant__ CUtensorMap tmap,
                const float* __restrict__ W1, const float* __restrict__ b1,
                const float* __restrict__ W2, const float* __restrict__ b2,
                const float* __restrict__ gamma, const float* __restrict__ beta,
                float* __restrict__ out, int ntok)
{
    extern __shared__ char smem_raw[];
    char* smem = (char*)(((uintptr_t)smem_raw + 1023) & ~(uintptr_t)1023);   // 1KB-align for SW128
    float* xbuf = (float*)smem;
    unsigned long long* Wp = (unsigned long long*)(smem + XBUF_BYTES);
    unsigned long long* mbar = (unsigned long long*)(smem + XBUF_BYTES + WP_BYTES);
    float* tail = (float*)(smem + XBUF_BYTES + WP_BYTES + 16 * 8);
    float* sW2 = tail;          // 64
    float* sb1 = tail + 64;     // 8
    float* sb2 = tail + 72;     // 8
    float* sg  = tail + 80;     // 8
    float* sbt = tail + 88;     // 8

    const int tid = threadIdx.x;
    const uint32_t mbar_su = (uint32_t)__cvta_generic_to_shared(mbar);

    // ---- one-time init: packed W1 dim-pairs + epilogue params + mbarriers ----
    {
        int e = tid * 4;
        #pragma unroll
        for (int q = 0; q < 4; q++) {
            int idx = e + q;
            int d = idx >> 3;
            int o = idx & 7;
            Wp[idx] = pk2(W1[o * DIM + 2 * d], W1[o * DIM + 2 * d + 1]);
        }
        if (tid < 64) sW2[tid] = W2[tid];
        if (tid < 8) { sb1[tid] = b1[tid]; sb2[tid] = b2[tid]; sg[tid] = gamma[tid]; sbt[tid] = beta[tid]; }
        if (tid < 16) mbar_init(mbar_su + tid * 8, 1);
    }
    __syncthreads();

    const int lane = tid & 31;
    const int warp = tid >> 5;
    const int warp_global = blockIdx.x * WARPS + warp;
    const int nwarps = gridDim.x * WARPS;
    const int ngroups = (ntok + TPW - 1) / TPW;

    float* wtile = xbuf + warp * 2 * (TILE_BYTES / 4);
    const uint32_t wtile_su = (uint32_t)__cvta_generic_to_shared(wtile);
    const uint32_t mymbar = mbar_su + warp * 16;            // 2 mbarriers per warp
    EpiParams ep{sW2, sb1, sb2, sg, sbt};

    const ulonglong2* Wp2 = (const ulonglong2*)Wp;
    const float* myrow = wtile + lane * CHUNK;              // lane's row within stage 0
    const int l7 = lane & 7;

    uint32_t ph0 = 0, ph1 = 0;                               // mbarrier phase per stage

    for (int g = warp_global; g < ngroups; g += nwarps) {
        const int base = g * TPW;

        // ---- issue chunk c into stage s: ONE TMA op (lane 0) ----
        auto stage_cp = [&](int c, int s) {
            if (lane == 0) {
                uint32_t mb = mymbar + s * 8;
                mbar_expect_tx(mb, TILE_BYTES);
                tma_load_2d(wtile_su + s * TILE_BYTES, &tmap, c * CHUNK, base, mb);
            }
        };

        unsigned long long acc[OUT];
        #pragma unroll
        for (int o = 0; o < OUT; o++) acc[o] = 0ull;

        // ---- compute chunk c from stage s (SW128: piece i at phys i^(lane&7)) ----
        auto compute = [&](int c, int s) {
            const float* r = myrow + s * (TILE_BYTES / 4);
            #pragma unroll
            for (int i = 0; i < 8; i++) {
                ulonglong2 xv = *(const ulonglong2*)(r + ((i ^ l7) << 2));
                const int dpg = c * 16 + 2 * i;
                const ulonglong2* w = Wp2 + (size_t)dpg * 4;
                {
                    ulonglong2 w0 = w[0];
                    acc[0] = fma2(xv.x, w0.x, acc[0]);
                    acc[1] = fma2(xv.x, w0.y, acc[1]);
                    ulonglong2 w1 = w[1];
                    acc[2] = fma2(xv.x, w1.x, acc[2]);
                    acc[3] = fma2(xv.x, w1.y, acc[3]);
                    ulonglong2 w2 = w[2];
                    acc[4] = fma2(xv.x, w2.x, acc[4]);
                    acc[5] = fma2(xv.x, w2.y, acc[5]);
                    ulonglong2 w3 = w[3];
                    acc[6] = fma2(xv.x, w3.x, acc[6]);
                    acc[7] = fma2(xv.x, w3.y, acc[7]);
                }
                {
                    ulonglong2 w4 = w[4];
                    acc[0] = fma2(xv.y, w4.x, acc[0]);
                    acc[1] = fma2(xv.y, w4.y, acc[1]);
                    ulonglong2 w5 = w[5];
                    acc[2] = fma2(xv.y, w5.x, acc[2]);
                    acc[3] = fma2(xv.y, w5.y, acc[3]);
                    ulonglong2 w6 = w[6];
                    acc[4] = fma2(xv.y, w6.x, acc[4]);
                    acc[5] = fma2(xv.y, w6.y, acc[5]);
                    ulonglong2 w7 = w[7];
                    acc[6] = fma2(xv.y, w7.x, acc[6]);
                    acc[7] = fma2(xv.y, w7.y, acc[7]);
                }
            }
        };

        // ---- 2-stage TMA pipeline ----
        stage_cp(0, 0);
        #pragma unroll
        for (int c = 0; c < NCHUNK; c++) {
            if (c + 1 < NCHUNK) stage_cp(c + 1, (c + 1) & 1);
            const int s = c & 1;
            if (s == 0) { mbar_wait(mymbar, ph0); ph0 ^= 1; }
            else        { mbar_wait(mymbar + 8, ph1); ph1 ^= 1; }
            compute(c, s);
            __syncwarp();
        }

        // ---- epilogue: this thread owns token base+lane (OOB rows were zero-filled) ----
        const int tok = base + lane;
        if (tok < ntok) epilogue(acc, ep, out, tok);
        __syncwarp();
    }
}

extern "C" void kernel_launch(void* const* d_in, const int* in_sizes, int n_in,
                              void* d_out, int out_size)
{
    const float* x     = (const float*)d_in[0];
    const float* W1    = (const float*)d_in[1];
    const float* b1    = (const float*)d_in[2];
    const float* W2    = (const float*)d_in[3];
    const float* b2    = (const float*)d_in[4];
    const float* gamma = (const float*)d_in[5];
    const float* beta  = (const float*)d_in[6];
    float* out = (float*)d_out;

    int ntok = in_sizes[0] / DIM;               // 262144 for the bench shape

    // ---- build TMA descriptor (driver entry point via runtime; no -lcuda link) ----
    typedef CUresult (*PFN_enc)(CUtensorMap*, CUtensorMapDataType, cuuint32_t, void*,
                                const cuuint64_t*, const cuuint64_t*, const cuuint32_t*,
                                const cuuint32_t*, CUtensorMapInterleave, CUtensorMapSwizzle,
                                CUtensorMapL2promotion, CUtensorMapFloatOOBfill);
    void* sym = nullptr;
    cudaDriverEntryPointQueryResult qst;
    cudaGetDriverEntryPoint("cuTensorMapEncodeTiled", &sym, cudaEnableDefault, &qst);
    PFN_enc enc = (PFN_enc)sym;

    CUtensorMap tmap;
    cuuint64_t dims[2]    = {(cuuint64_t)DIM, (cuuint64_t)ntok};
    cuuint64_t strides[1] = {(cuuint64_t)DIM * 4};            // 1024B row stride
    cuuint32_t box[2]     = {(cuuint32_t)CHUNK, (cuuint32_t)TPW};   // 32 floats (128B) x 32 rows
    cuuint32_t es[2]      = {1, 1};
    enc(&tmap, CU_TENSOR_MAP_DATA_TYPE_FLOAT32, 2, (void*)x,
        dims, strides, box, es,
        CU_TENSOR_MAP_INTERLEAVE_NONE, CU_TENSOR_MAP_SWIZZLE_128B,
        CU_TENSOR_MAP_L2_PROMOTION_L2_128B, CU_TENSOR_MAP_FLOAT_OOB_FILL_NONE);

    int ngroups = (ntok + TPW - 1) / TPW;       // warp-groups of 32 tokens
    int blocks = (ngroups + WARPS - 1) / WARPS;
    if (blocks > 1024) blocks = 1024;
    if (blocks < 1) blocks = 1;

    cudaFuncSetAttribute(ffn_kernel, cudaFuncAttributeMaxDynamicSharedMemorySize, SMEM_TOTAL);
    ffn_kernel<<<blocks, 256, SMEM_TOTAL>>>(tmap, W1, b1, W2, b2, gamma, beta, out, ntok);
}